// round 3
// baseline (speedup 1.0000x reference)
#include <cuda_runtime.h>

// Fixed problem shape
#define NB 2048
#define ND 16384
#define RSPLIT 64
#define ROWS_PER (NB / RSPLIT)        // 32 rows per partial block
#define FIN_BLOCKS 32                 // 32 blocks * 256 thr * 2 cols = 16384
#define CHUNKS 8
#define CCOLS (ND / CHUNKS)           // 2048 columns per chunk
#define CF4 (CCOLS / 4)               // 512 float4 per chunk
#define ROWS_BLK 16                   // rows per punish block (8 warps x 2)
#define PUN_GY (NB / ROWS_BLK)        // 128

// Scratch (__device__ globals; no allocation allowed)
__device__ float g_psum[RSPLIT * ND];
__device__ float g_psq [RSPLIT * ND];
__device__ float g_nmean[ND];
__device__ float g_nvar [ND];
__device__ float g_varpart[FIN_BLOCKS];
__device__ float g_addend;
__device__ int   g_fcnt;                       // zero-init; self-resetting
__device__ unsigned long long g_rowkey[NB];    // zero-init; self-resetting
__device__ int   g_rowcnt[NB];                 // zero-init; self-resetting

// ---------------------------------------------------------------------------
// Pass 1: per-(rowchunk, column) partial sum / sumsq.
// grid = (ND/1024, RSPLIT), block = 256, 4 cols/thread, 32 rows/block.
// ---------------------------------------------------------------------------
__global__ void __launch_bounds__(256) k_colstats_partial(const float* __restrict__ h) {
    const int c  = (blockIdx.x * 256 + threadIdx.x) * 4;
    const int r0 = blockIdx.y * ROWS_PER;
    float4 s = make_float4(0.f, 0.f, 0.f, 0.f);
    float4 q = make_float4(0.f, 0.f, 0.f, 0.f);
    const float4* hp = reinterpret_cast<const float4*>(h + (size_t)r0 * ND + c);
    const size_t stride4 = ND / 4;
#pragma unroll 8
    for (int r = 0; r < ROWS_PER; ++r) {
        float4 v = __ldcs(&hp[(size_t)r * stride4]);
        s.x += v.x;       s.y += v.y;       s.z += v.z;       s.w += v.w;
        q.x += v.x * v.x; q.y += v.y * v.y; q.z += v.z * v.z; q.w += v.w * v.w;
    }
    *reinterpret_cast<float4*>(g_psum + (size_t)blockIdx.y * ND + c) = s;
    *reinterpret_cast<float4*>(g_psq  + (size_t)blockIdx.y * ND + c) = q;
}

// ---------------------------------------------------------------------------
// Pass 2: finish stats -> new_mean, new_var; fused mean(new_var)/100 via
// last-block reduction (self-resetting counter; deterministic fixed tree).
// grid = FIN_BLOCKS (32), block = 256, 2 cols/thread.
// ---------------------------------------------------------------------------
__global__ void __launch_bounds__(256) k_colstats_finish(const float* __restrict__ hmean,
                                                         const float* __restrict__ hvar) {
    const int c = (blockIdx.x * 256 + threadIdx.x) * 2;
    float2 s = make_float2(0.f, 0.f);
    float2 q = make_float2(0.f, 0.f);
#pragma unroll 8
    for (int i = 0; i < RSPLIT; ++i) {
        float2 a = *reinterpret_cast<const float2*>(g_psum + (size_t)i * ND + c);
        float2 b = *reinterpret_cast<const float2*>(g_psq  + (size_t)i * ND + c);
        s.x += a.x; s.y += a.y;
        q.x += b.x; q.y += b.y;
    }
    const float invB    = 1.0f / (float)NB;
    const float U       = 10.0f;
    const float inv11   = 1.0f / 11.0f;
    const float inv1p1  = 1.0f / 1.1f;
    const float invDen  = 1.0f / (U + 1.0f - invB);
    const float coefOld = U - invB;

    float2 hm = *reinterpret_cast<const float2*>(hmean + c);
    float2 hv = *reinterpret_cast<const float2*>(hvar  + c);

    float2 nm, nv;
    {
        float mu, var, d;
        mu = s.x * invB; var = q.x * invB - mu * mu; d = mu - hm.x;
        nv.x = (hv.x * coefOld + var + d * d * inv1p1) * invDen;
        nm.x = (hm.x * U + mu) * inv11;
        mu = s.y * invB; var = q.y * invB - mu * mu; d = mu - hm.y;
        nv.y = (hv.y * coefOld + var + d * d * inv1p1) * invDen;
        nm.y = (hm.y * U + mu) * inv11;
    }
    *reinterpret_cast<float2*>(g_nmean + c) = nm;
    *reinterpret_cast<float2*>(g_nvar  + c) = nv;

    __shared__ float sred[256];
    sred[threadIdx.x] = nv.x + nv.y;
    __syncthreads();
    for (int off = 128; off > 0; off >>= 1) {
        if (threadIdx.x < off) sred[threadIdx.x] += sred[threadIdx.x + off];
        __syncthreads();
    }

    __shared__ int is_last;
    if (threadIdx.x == 0) {
        g_varpart[blockIdx.x] = sred[0];
        __threadfence();
        int old = atomicAdd(&g_fcnt, 1);
        is_last = (old == FIN_BLOCKS - 1) ? 1 : 0;
    }
    __syncthreads();
    if (is_last && threadIdx.x < 32) {
        __threadfence();                      // acquire side
        float v = g_varpart[threadIdx.x];     // FIN_BLOCKS == 32
#pragma unroll
        for (int off = 16; off > 0; off >>= 1)
            v += __shfl_down_sync(0xFFFFFFFFu, v, off);
        if (threadIdx.x == 0) {
            g_addend = (v / (float)ND) * 0.01f;
            g_fcnt = 0;                       // reset for next graph replay
        }
    }
}

// ---------------------------------------------------------------------------
// Pass 3: copy + per-row argmax of (h-nm)^2 * inv, column-chunked.
// grid = (CHUNKS, PUN_GY), block = 256 (8 warps, warp-per-row, 2 rows each).
// mean/inv cached in smem (kills the 256MB L2 re-read). Cross-chunk combine
// via u64 atomicMax keys + per-row arrival counter (8th block writes winner).
// Key = score_bits<<32 | (0xFFFFFFFF - col): max => max score, ties => low col.
// ---------------------------------------------------------------------------
__global__ void __launch_bounds__(256) k_punish(const float* __restrict__ h,
                                                float* __restrict__ out) {
    __shared__ float4 sm_m[CF4];
    __shared__ float4 sm_i[CF4];
    const int tid   = threadIdx.x;
    const int cbase = blockIdx.x * CCOLS;
    const float a   = g_addend;

    const float4* m4 = reinterpret_cast<const float4*>(g_nmean + cbase);
    const float4* v4 = reinterpret_cast<const float4*>(g_nvar  + cbase);
#pragma unroll
    for (int j = tid; j < CF4; j += 256) {
        float4 m = __ldg(&m4[j]);
        float4 v = __ldg(&v4[j]);
        float4 iv;
        iv.x = 1.0f / (v.x + a);
        iv.y = 1.0f / (v.y + a);
        iv.z = 1.0f / (v.z + a);
        iv.w = 1.0f / (v.w + a);
        sm_m[j] = m;
        sm_i[j] = iv;
    }
    __syncthreads();

    const int wid  = tid >> 5;
    const int lane = tid & 31;

#pragma unroll
    for (int rr = 0; rr < ROWS_BLK / 8; ++rr) {
        const int row = blockIdx.y * ROWS_BLK + rr * 8 + wid;
        const float4* hrow = reinterpret_cast<const float4*>(h   + (size_t)row * ND + cbase);
        float4*       orow = reinterpret_cast<float4*>      (out + (size_t)row * ND + cbase);

        float best = -1.0f;
        int   bcol = cbase;
#pragma unroll
        for (int j = 0; j < CF4 / 32; ++j) {          // 16 iterations
            const int idx = j * 32 + lane;            // coalesced across warp
            float4 hv = __ldcs(&hrow[idx]);
            float4 m  = sm_m[idx];
            float4 iv = sm_i[idx];
            __stcs(&orow[idx], hv);
            const int c = cbase + idx * 4;
            float d, sc;
            d = hv.x - m.x; sc = d * d * iv.x; if (sc > best) { best = sc; bcol = c;     }
            d = hv.y - m.y; sc = d * d * iv.y; if (sc > best) { best = sc; bcol = c + 1; }
            d = hv.z - m.z; sc = d * d * iv.z; if (sc > best) { best = sc; bcol = c + 2; }
            d = hv.w - m.w; sc = d * d * iv.w; if (sc > best) { best = sc; bcol = c + 3; }
        }

        unsigned long long key =
            ((unsigned long long)__float_as_uint(best) << 32) |
            (unsigned long long)(0xFFFFFFFFu - (unsigned)bcol);
#pragma unroll
        for (int off = 16; off > 0; off >>= 1) {
            unsigned long long o = __shfl_xor_sync(0xFFFFFFFFu, key, off);
            if (o > key) key = o;
        }

        // make this warp's out-stores visible before signaling arrival
        __threadfence();
        __syncwarp();
        if (lane == 0) {
            atomicMax(&g_rowkey[row], key);
            __threadfence();
            int old = atomicAdd(&g_rowcnt[row], 1);
            if (old == CHUNKS - 1) {
                __threadfence();              // acquire side
                unsigned long long k = g_rowkey[row];
                g_rowkey[row] = 0ULL;         // reset for next graph replay
                g_rowcnt[row] = 0;
                int w = (int)(0xFFFFFFFFu - (unsigned)(k & 0xFFFFFFFFull));
                out[(size_t)row * ND + w] = g_nmean[w];
            }
        }
    }
}

// ---------------------------------------------------------------------------
extern "C" void kernel_launch(void* const* d_in, const int* in_sizes, int n_in,
                              void* d_out, int out_size) {
    const float* h     = (const float*)d_in[0];
    const float* hmean = (const float*)d_in[1];
    const float* hvar  = (const float*)d_in[2];
    float* out = (float*)d_out;
    (void)in_sizes; (void)n_in; (void)out_size;

    dim3 g1(ND / (256 * 4), RSPLIT);
    k_colstats_partial<<<g1, 256>>>(h);
    k_colstats_finish<<<FIN_BLOCKS, 256>>>(hmean, hvar);
    k_punish<<<dim3(CHUNKS, PUN_GY), 256>>>(h, out);
}

// round 4
// speedup vs baseline: 1.5548x; 1.5548x over previous
#include <cuda_runtime.h>

// Fixed problem shape
#define NB 2048
#define ND 16384
#define RSPLIT 64
#define ROWS_PER (NB / RSPLIT)        // 32 rows per partial block
#define FIN_BLOCKS 32                 // 32 blocks * 256 thr * 2 cols = 16384
#define SI_BLOCKS 64                  // scalar+inv kernel: 64 blocks * 256 = 16384 cols

// Scratch (__device__ globals; no allocation allowed)
__device__ float g_psum[RSPLIT * ND];
__device__ float g_psq [RSPLIT * ND];
__device__ float g_nmean[ND];
__device__ float g_nvar [ND];
__device__ float g_inv  [ND];
__device__ float g_varpart[FIN_BLOCKS];

// ---------------------------------------------------------------------------
// Pass 1: per-(rowchunk, column) partial sum / sumsq.
// grid = (ND/1024, RSPLIT), block = 256, 4 cols/thread, 32 rows/block.
// Default (evict-normal) loads: keep h resident in L2 for the punish re-read.
// ---------------------------------------------------------------------------
__global__ void __launch_bounds__(256) k_colstats_partial(const float* __restrict__ h) {
    const int c  = (blockIdx.x * 256 + threadIdx.x) * 4;
    const int r0 = blockIdx.y * ROWS_PER;
    float4 s = make_float4(0.f, 0.f, 0.f, 0.f);
    float4 q = make_float4(0.f, 0.f, 0.f, 0.f);
    const float4* hp = reinterpret_cast<const float4*>(h + (size_t)r0 * ND + c);
    const size_t stride4 = ND / 4;
#pragma unroll 8
    for (int r = 0; r < ROWS_PER; ++r) {
        float4 v = hp[(size_t)r * stride4];
        s.x += v.x;       s.y += v.y;       s.z += v.z;       s.w += v.w;
        q.x += v.x * v.x; q.y += v.y * v.y; q.z += v.z * v.z; q.w += v.w * v.w;
    }
    *reinterpret_cast<float4*>(g_psum + (size_t)blockIdx.y * ND + c) = s;
    *reinterpret_cast<float4*>(g_psq  + (size_t)blockIdx.y * ND + c) = q;
}

// ---------------------------------------------------------------------------
// Pass 2: finish stats -> new_mean, new_var; per-block partial of sum(new_var).
// grid = FIN_BLOCKS (32), block = 256, 2 cols/thread. Partials are L2-hot.
// ---------------------------------------------------------------------------
__global__ void __launch_bounds__(256) k_colstats_finish(const float* __restrict__ hmean,
                                                         const float* __restrict__ hvar) {
    const int c = (blockIdx.x * 256 + threadIdx.x) * 2;
    float2 s = make_float2(0.f, 0.f);
    float2 q = make_float2(0.f, 0.f);
#pragma unroll 8
    for (int i = 0; i < RSPLIT; ++i) {
        float2 a = *reinterpret_cast<const float2*>(g_psum + (size_t)i * ND + c);
        float2 b = *reinterpret_cast<const float2*>(g_psq  + (size_t)i * ND + c);
        s.x += a.x; s.y += a.y;
        q.x += b.x; q.y += b.y;
    }
    const float invB    = 1.0f / (float)NB;
    const float U       = 10.0f;
    const float inv11   = 1.0f / 11.0f;
    const float inv1p1  = 1.0f / 1.1f;
    const float invDen  = 1.0f / (U + 1.0f - invB);
    const float coefOld = U - invB;

    float2 hm = *reinterpret_cast<const float2*>(hmean + c);
    float2 hv = *reinterpret_cast<const float2*>(hvar  + c);

    float2 nm, nv;
    {
        float mu, var, d;
        mu = s.x * invB; var = q.x * invB - mu * mu; d = mu - hm.x;
        nv.x = (hv.x * coefOld + var + d * d * inv1p1) * invDen;
        nm.x = (hm.x * U + mu) * inv11;
        mu = s.y * invB; var = q.y * invB - mu * mu; d = mu - hm.y;
        nv.y = (hv.y * coefOld + var + d * d * inv1p1) * invDen;
        nm.y = (hm.y * U + mu) * inv11;
    }
    *reinterpret_cast<float2*>(g_nmean + c) = nm;
    *reinterpret_cast<float2*>(g_nvar  + c) = nv;

    __shared__ float sred[256];
    sred[threadIdx.x] = nv.x + nv.y;
    __syncthreads();
    for (int off = 128; off > 0; off >>= 1) {
        if (threadIdx.x < off) sred[threadIdx.x] += sred[threadIdx.x + off];
        __syncthreads();
    }
    if (threadIdx.x == 0) g_varpart[blockIdx.x] = sred[0];
}

// ---------------------------------------------------------------------------
// Pass 3 (fused scalar + inv): every block redundantly reduces the 32 varpart
// values (L2-hot) to get addend, then writes its slice of inv = 1/(nvar+a).
// grid = SI_BLOCKS (64), block = 256, 1 col/thread.
// ---------------------------------------------------------------------------
__global__ void __launch_bounds__(256) k_scalar_inv() {
    __shared__ float s_add;
    if (threadIdx.x < 32) {
        float v = g_varpart[threadIdx.x];   // FIN_BLOCKS == 32
#pragma unroll
        for (int off = 16; off > 0; off >>= 1)
            v += __shfl_down_sync(0xFFFFFFFFu, v, off);
        if (threadIdx.x == 0) s_add = (v / (float)ND) * 0.01f;
    }
    __syncthreads();
    const float a = s_add;
    const int c = blockIdx.x * 256 + threadIdx.x;
    g_inv[c] = 1.0f / (g_nvar[c] + a);
}

// ---------------------------------------------------------------------------
// Pass 4: per-row copy + argmax of (h-nm)^2 * inv + winner fixup.
// grid = NB, block = 256, one row per block. 4-way ILP, fmax-tree per float4,
// winner element resolved once per row by bitwise-identical recompute.
// h loads default (L2 hits from pass1 residency); out stores streaming.
// ---------------------------------------------------------------------------
__device__ __forceinline__ float score_of(float hv, float m, float iv) {
    float d = __fadd_rn(hv, -m);
    return __fmul_rn(__fmul_rn(d, d), iv);
}

__global__ void __launch_bounds__(256) k_punish(const float* __restrict__ h,
                                                float* __restrict__ out) {
    const int row = blockIdx.x;
    const int tid = threadIdx.x;

    const float4* hrow = reinterpret_cast<const float4*>(h   + (size_t)row * ND);
    float4*       orow = reinterpret_cast<float4*>      (out + (size_t)row * ND);
    const float4* m4p  = reinterpret_cast<const float4*>(g_nmean);
    const float4* i4p  = reinterpret_cast<const float4*>(g_inv);

    float best = -1.0f;   // scores >= 0
    int   bj   = tid;     // winning float4 index (ascending per thread)

#pragma unroll
    for (int it = 0; it < ND / (256 * 4 * 4); ++it) {   // 4 iterations, 4 float4s each
        const int jb = it * 1024 + tid;
        const int j0 = jb, j1 = jb + 256, j2 = jb + 512, j3 = jb + 768;

        // front-batched loads (MLP)
        float4 h0 = hrow[j0];
        float4 h1 = hrow[j1];
        float4 h2 = hrow[j2];
        float4 h3 = hrow[j3];
        float4 m0 = __ldg(&m4p[j0]);
        float4 m1 = __ldg(&m4p[j1]);
        float4 m2 = __ldg(&m4p[j2]);
        float4 m3 = __ldg(&m4p[j3]);
        float4 v0 = __ldg(&i4p[j0]);
        float4 v1 = __ldg(&i4p[j1]);
        float4 v2 = __ldg(&i4p[j2]);
        float4 v3 = __ldg(&i4p[j3]);

        __stcs(&orow[j0], h0);
        __stcs(&orow[j1], h1);
        __stcs(&orow[j2], h2);
        __stcs(&orow[j3], h3);

        float mx;
        mx = fmaxf(fmaxf(score_of(h0.x, m0.x, v0.x), score_of(h0.y, m0.y, v0.y)),
                   fmaxf(score_of(h0.z, m0.z, v0.z), score_of(h0.w, m0.w, v0.w)));
        if (mx > best) { best = mx; bj = j0; }
        mx = fmaxf(fmaxf(score_of(h1.x, m1.x, v1.x), score_of(h1.y, m1.y, v1.y)),
                   fmaxf(score_of(h1.z, m1.z, v1.z), score_of(h1.w, m1.w, v1.w)));
        if (mx > best) { best = mx; bj = j1; }
        mx = fmaxf(fmaxf(score_of(h2.x, m2.x, v2.x), score_of(h2.y, m2.y, v2.y)),
                   fmaxf(score_of(h2.z, m2.z, v2.z), score_of(h2.w, m2.w, v2.w)));
        if (mx > best) { best = mx; bj = j2; }
        mx = fmaxf(fmaxf(score_of(h3.x, m3.x, v3.x), score_of(h3.y, m3.y, v3.y)),
                   fmaxf(score_of(h3.z, m3.z, v3.z), score_of(h3.w, m3.w, v3.w)));
        if (mx > best) { best = mx; bj = j3; }
    }

    // resolve which element of the winning float4 achieved best (first match).
    // Bitwise-identical recompute: same __fadd_rn/__fmul_rn sequence as above.
    int bidx;
    {
        float4 hv = hrow[bj];           // L1 hit
        float4 m  = __ldg(&m4p[bj]);
        float4 iv = __ldg(&i4p[bj]);
        float s0 = score_of(hv.x, m.x, iv.x);
        float s1 = score_of(hv.y, m.y, iv.y);
        float s2 = score_of(hv.z, m.z, iv.z);
        bidx = bj * 4 + ((s0 == best) ? 0 : (s1 == best) ? 1 : (s2 == best) ? 2 : 3);
    }

    __shared__ float sbest[256];
    __shared__ int   sidx[256];
    sbest[tid] = best;
    sidx[tid]  = bidx;
    __syncthreads();
    for (int off = 128; off > 0; off >>= 1) {
        if (tid < off) {
            float ob = sbest[tid + off];
            int   oi = sidx[tid + off];
            if (ob > sbest[tid] || (ob == sbest[tid] && oi < sidx[tid])) {
                sbest[tid] = ob;
                sidx[tid]  = oi;
            }
        }
        __syncthreads();
    }
    if (tid == 0) {
        int w = sidx[0];
        out[(size_t)row * ND + w] = g_nmean[w];
    }
}

// ---------------------------------------------------------------------------
extern "C" void kernel_launch(void* const* d_in, const int* in_sizes, int n_in,
                              void* d_out, int out_size) {
    const float* h     = (const float*)d_in[0];
    const float* hmean = (const float*)d_in[1];
    const float* hvar  = (const float*)d_in[2];
    float* out = (float*)d_out;
    (void)in_sizes; (void)n_in; (void)out_size;

    dim3 g1(ND / (256 * 4), RSPLIT);
    k_colstats_partial<<<g1, 256>>>(h);
    k_colstats_finish<<<FIN_BLOCKS, 256>>>(hmean, hvar);
    k_scalar_inv<<<SI_BLOCKS, 256>>>();
    k_punish<<<NB, 256>>>(h, out);
}